// round 1
// baseline (speedup 1.0000x reference)
#include <cuda_runtime.h>
#include <cuda_bf16.h>

#define NN 100000
#define NE 800000
#define DM 128

// ---------------- scratch (device globals: no cudaMalloc allowed) ----------------
__device__ float g_deg[NN];
__device__ float g_dis[NN];
__device__ int   g_cnt[NN];
__device__ int   g_off[NN + 1];
__device__ int   g_cur[NN];
__device__ int   g_src[2 * NE];
__device__ float g_w[2 * NE];
__device__ float g_agg[(size_t)NN * DM];
__device__ float g_buf1[(size_t)NN * DM];

// ---------------- build kernels ----------------
__global__ void k_zero() {
    int i = blockIdx.x * blockDim.x + threadIdx.x;
    if (i < NN) { g_deg[i] = 0.f; g_cnt[i] = 0; }
}

__global__ void k_deg(const int* __restrict__ s, const int* __restrict__ r,
                      const float* __restrict__ e) {
    int i = blockIdx.x * blockDim.x + threadIdx.x;
    if (i < NE) {
        int a = s[i], b = r[i];
        float ev = e[i];
        atomicAdd(&g_deg[a], ev);
        atomicAdd(&g_deg[b], ev);
        atomicAdd(&g_cnt[a], 1);
        atomicAdd(&g_cnt[b], 1);
    }
}

__global__ void k_dis() {
    int i = blockIdx.x * blockDim.x + threadIdx.x;
    if (i < NN) {
        float d = g_deg[i];
        g_dis[i] = (d > 0.f) ? rsqrtf(d) : 0.f;
    }
}

// single-block exclusive scan of g_cnt -> g_off (and init g_cur)
__global__ void k_scan() {
    __shared__ int sh[1024];
    int tid = threadIdx.x;
    const int CH = (NN + 1023) / 1024;  // 98
    int st = tid * CH;
    int en = st + CH; if (en > NN) en = NN;
    int s = 0;
    for (int i = st; i < en; i++) s += g_cnt[i];
    sh[tid] = s;
    __syncthreads();
    // Kogge-Stone inclusive scan
    for (int d = 1; d < 1024; d <<= 1) {
        int t = 0;
        if (tid >= d) t = sh[tid - d];
        __syncthreads();
        sh[tid] += t;
        __syncthreads();
    }
    int run = sh[tid] - s;  // exclusive prefix for this chunk
    for (int i = st; i < en; i++) {
        g_off[i] = run;
        g_cur[i] = run;
        run += g_cnt[i];
    }
    if (tid == 1023) g_off[NN] = sh[1023];
}

__global__ void k_fill(const int* __restrict__ s, const int* __restrict__ r,
                       const float* __restrict__ e) {
    int i = blockIdx.x * blockDim.x + threadIdx.x;
    if (i < NE) {
        int a = s[i], b = r[i];
        float w = g_dis[a] * e[i] * g_dis[b];  // symmetric for both directions
        int p = atomicAdd(&g_cur[b], 1);  // edge a->b aggregated at b
        g_src[p] = a; g_w[p] = w;
        int q = atomicAdd(&g_cur[a], 1);  // edge b->a aggregated at a
        g_src[q] = b; g_w[q] = w;
    }
}

// ---------------- aggregation: one warp per node, float4 per lane ----------------
__global__ void k_agg(const float* __restrict__ x) {
    int warp = (blockIdx.x * blockDim.x + threadIdx.x) >> 5;
    int lane = threadIdx.x & 31;
    if (warp >= NN) return;
    int beg = g_off[warp], end = g_off[warp + 1];
    float4 acc = make_float4(0.f, 0.f, 0.f, 0.f);
    const float4* __restrict__ x4 = (const float4*)x;
    for (int j = beg; j < end; j++) {
        int src = g_src[j];
        float w = g_w[j];
        float4 v = __ldg(&x4[(size_t)src * 32 + lane]);
        acc.x += w * v.x;
        acc.y += w * v.y;
        acc.z += w * v.z;
        acc.w += w * v.w;
    }
    ((float4*)g_agg)[(size_t)warp * 32 + lane] = acc;
}

// ---------------- fused GEMM + bias + residual ----------------
// out[m,:] = res[m,:] + g_agg[m,:] @ W + b
// 128x128 output tile per block, 256 threads, 8x8 micro-tile per thread.
#define AP 132  // padded A-tile row stride (float4-aligned, avoids worst conflicts)
__global__ void __launch_bounds__(256, 1)
k_gemm(const float* __restrict__ Wm, const float* __restrict__ bias,
       const float* __restrict__ res, float* __restrict__ out) {
    extern __shared__ float sh[];
    float (*As)[AP]  = (float(*)[AP])sh;
    float (*Ws)[DM]  = (float(*)[DM])(sh + 128 * AP);

    int tid = threadIdx.x;
    int rowBase = blockIdx.x * 128;

    // load W (128x128) : 4096 float4 / 256 threads = 16 each
    const float4* W4 = (const float4*)Wm;
    float4* Ws4 = (float4*)Ws;
#pragma unroll
    for (int i = 0; i < 16; i++) Ws4[tid + i * 256] = __ldg(&W4[tid + i * 256]);

    // load A tile (128 rows x 128 k) row-major into padded smem
    const float4* A4 = (const float4*)g_agg;
#pragma unroll
    for (int i = 0; i < 16; i++) {
        int f = tid + i * 256;        // 0..4095
        int row = f >> 5;             // 0..127
        int kq = f & 31;              // float4 index along k
        int grow = rowBase + row;
        float4 v = make_float4(0.f, 0.f, 0.f, 0.f);
        if (grow < NN) v = __ldg(&A4[(size_t)grow * 32 + kq]);
        *((float4*)&As[row][kq * 4]) = v;
    }
    __syncthreads();

    int tx = tid & 15, ty = tid >> 4;
    int r0 = ty * 8, c0 = tx * 8;

    float acc[8][8];
#pragma unroll
    for (int i = 0; i < 8; i++)
#pragma unroll
        for (int j = 0; j < 8; j++) acc[i][j] = 0.f;

#pragma unroll 4
    for (int k = 0; k < 128; k++) {
        float a[8];
#pragma unroll
        for (int i = 0; i < 8; i++) a[i] = As[r0 + i][k];
        float4 w0 = *((float4*)&Ws[k][c0]);
        float4 w1 = *((float4*)&Ws[k][c0 + 4]);
        float w[8] = {w0.x, w0.y, w0.z, w0.w, w1.x, w1.y, w1.z, w1.w};
#pragma unroll
        for (int i = 0; i < 8; i++)
#pragma unroll
            for (int j = 0; j < 8; j++) acc[i][j] += a[i] * w[j];
    }

    // epilogue: + residual + bias
    float4 bv0 = *((const float4*)&bias[c0]);
    float4 bv1 = *((const float4*)&bias[c0 + 4]);
#pragma unroll
    for (int i = 0; i < 8; i++) {
        int grow = rowBase + r0 + i;
        if (grow < NN) {
            const float4* rp = (const float4*)&res[(size_t)grow * DM + c0];
            float4 rv0 = __ldg(&rp[0]);
            float4 rv1 = __ldg(&rp[1]);
            float4 o0 = make_float4(rv0.x + acc[i][0] + bv0.x,
                                    rv0.y + acc[i][1] + bv0.y,
                                    rv0.z + acc[i][2] + bv0.z,
                                    rv0.w + acc[i][3] + bv0.w);
            float4 o1 = make_float4(rv1.x + acc[i][4] + bv1.x,
                                    rv1.y + acc[i][5] + bv1.y,
                                    rv1.z + acc[i][6] + bv1.z,
                                    rv1.w + acc[i][7] + bv1.w);
            float4* op = (float4*)&out[(size_t)grow * DM + c0];
            op[0] = o0;
            op[1] = o1;
        }
    }
}

// ---------------- launch ----------------
extern "C" void kernel_launch(void* const* d_in, const int* in_sizes, int n_in,
                              void* d_out, int out_size) {
    const float* nodes     = (const float*)d_in[0];
    const int*   senders   = (const int*)d_in[1];
    const int*   receivers = (const int*)d_in[2];
    const float* edges     = (const float*)d_in[3];
    const float* W1 = (const float*)d_in[4];
    const float* b1 = (const float*)d_in[5];
    const float* W2 = (const float*)d_in[6];
    const float* b2 = (const float*)d_in[7];
    float* out = (float*)d_out;

    float* buf1 = nullptr;
    cudaGetSymbolAddress((void**)&buf1, g_buf1);

    const size_t SMEM_GEMM = (size_t)(128 * AP + 128 * DM) * sizeof(float);
    cudaFuncSetAttribute(k_gemm, cudaFuncAttributeMaxDynamicSharedMemorySize,
                         (int)SMEM_GEMM);

    const int T = 256;
    // CSR + degree build (shared by both layers)
    k_zero<<<(NN + T - 1) / T, T>>>();
    k_deg<<<(NE + T - 1) / T, T>>>(senders, receivers, edges);
    k_dis<<<(NN + T - 1) / T, T>>>();
    k_scan<<<1, 1024>>>();
    k_fill<<<(NE + T - 1) / T, T>>>(senders, receivers, edges);

    const int AGG_GRID = (NN * 32 + T - 1) / T;   // one warp per node
    const int GEMM_GRID = (NN + 127) / 128;

    // layer 1: nodes -> buf1
    k_agg<<<AGG_GRID, T>>>(nodes);
    k_gemm<<<GEMM_GRID, T, SMEM_GEMM>>>(W1, b1, nodes, buf1);

    // layer 2: buf1 -> out
    k_agg<<<AGG_GRID, T>>>(buf1);
    k_gemm<<<GEMM_GRID, T, SMEM_GEMM>>>(W2, b2, buf1, out);
}

// round 2
// speedup vs baseline: 1.2929x; 1.2929x over previous
#include <cuda_runtime.h>
#include <cuda_bf16.h>

#define NN 100000
#define NE 800000
#define DM 128

typedef unsigned long long u64;

// ---------------- scratch (device globals: no cudaMalloc allowed) ----------------
__device__ float g_deg[NN];
__device__ float g_dis[NN];
__device__ int   g_cnt[NN];
__device__ int   g_off[NN + 1];
__device__ int   g_cur[NN];
__device__ int   g_src[2 * NE];
__device__ float g_w[2 * NE];
__device__ float g_agg[(size_t)NN * DM];
__device__ float g_buf1[(size_t)NN * DM];

#define SCB 256
#define SNB ((NN + SCB - 1) / SCB)   // 391 scan blocks
__device__ int g_bsum[SNB];
__device__ int g_boff[SNB];

// ---------------- build kernels ----------------
__global__ void k_zero() {
    int i = blockIdx.x * blockDim.x + threadIdx.x;
    if (i < NN) { g_deg[i] = 0.f; g_cnt[i] = 0; }
}

__global__ void k_deg(const int* __restrict__ s, const int* __restrict__ r,
                      const float* __restrict__ e) {
    int i = blockIdx.x * blockDim.x + threadIdx.x;
    if (i < NE) {
        int a = s[i], b = r[i];
        float ev = e[i];
        atomicAdd(&g_deg[a], ev);
        atomicAdd(&g_deg[b], ev);
        atomicAdd(&g_cnt[a], 1);
        atomicAdd(&g_cnt[b], 1);
    }
}

__global__ void k_dis() {
    int i = blockIdx.x * blockDim.x + threadIdx.x;
    if (i < NN) {
        float d = g_deg[i];
        g_dis[i] = (d > 0.f) ? rsqrtf(d) : 0.f;
    }
}

// ---------------- parallel 3-phase scan ----------------
__global__ void k_scan1() {
    __shared__ int sh[SCB];
    int i = blockIdx.x * SCB + threadIdx.x;
    int v = (i < NN) ? g_cnt[i] : 0;
    sh[threadIdx.x] = v;
    __syncthreads();
    for (int d = SCB / 2; d > 0; d >>= 1) {
        if (threadIdx.x < d) sh[threadIdx.x] += sh[threadIdx.x + d];
        __syncthreads();
    }
    if (threadIdx.x == 0) g_bsum[blockIdx.x] = sh[0];
}

__global__ void k_scan2() {
    __shared__ int sh[512];
    int t = threadIdx.x;
    int v = (t < SNB) ? g_bsum[t] : 0;
    sh[t] = v;
    __syncthreads();
    for (int d = 1; d < 512; d <<= 1) {
        int x = 0;
        if (t >= d) x = sh[t - d];
        __syncthreads();
        sh[t] += x;
        __syncthreads();
    }
    if (t < SNB) g_boff[t] = sh[t] - v;        // exclusive
    if (t == SNB - 1) g_off[NN] = sh[t];       // total
}

__global__ void k_scan3() {
    __shared__ int sh[SCB];
    int i = blockIdx.x * SCB + threadIdx.x;
    int t = threadIdx.x;
    int v = (i < NN) ? g_cnt[i] : 0;
    sh[t] = v;
    __syncthreads();
    for (int d = 1; d < SCB; d <<= 1) {
        int x = 0;
        if (t >= d) x = sh[t - d];
        __syncthreads();
        sh[t] += x;
        __syncthreads();
    }
    if (i < NN) {
        int excl = sh[t] - v + g_boff[blockIdx.x];
        g_off[i] = excl;
        g_cur[i] = excl;
    }
}

__global__ void k_fill(const int* __restrict__ s, const int* __restrict__ r,
                       const float* __restrict__ e) {
    int i = blockIdx.x * blockDim.x + threadIdx.x;
    if (i < NE) {
        int a = s[i], b = r[i];
        float w = g_dis[a] * e[i] * g_dis[b];  // symmetric for both directions
        int p = atomicAdd(&g_cur[b], 1);       // edge a->b aggregated at b
        g_src[p] = a; g_w[p] = w;
        int q = atomicAdd(&g_cur[a], 1);       // edge b->a aggregated at a
        g_src[q] = b; g_w[q] = w;
    }
}

// ---------------- aggregation: one warp per node, float4 per lane ----------------
__global__ void k_agg(const float* __restrict__ x) {
    int warp = (blockIdx.x * blockDim.x + threadIdx.x) >> 5;
    int lane = threadIdx.x & 31;
    if (warp >= NN) return;
    int beg = g_off[warp], end = g_off[warp + 1];
    float4 acc = make_float4(0.f, 0.f, 0.f, 0.f);
    const float4* __restrict__ x4 = (const float4*)x;
    for (int j = beg; j < end; j++) {
        int src = g_src[j];
        float w = g_w[j];
        float4 v = __ldg(&x4[(size_t)src * 32 + lane]);
        acc.x += w * v.x;
        acc.y += w * v.y;
        acc.z += w * v.z;
        acc.w += w * v.w;
    }
    ((float4*)g_agg)[(size_t)warp * 32 + lane] = acc;
}

// ---------------- fused GEMM + bias + residual, packed fp32x2 FMA ----------------
// out[m,:] = res[m,:] + g_agg[m,:] @ W + b
// 128x128 tile / block, 256 threads, 8x8 micro-tile, acc packed along K.
#define SW 132   // smem row stride (floats): 132*4B = 528B, 16B-aligned, conflict-min

__device__ __forceinline__ u64 fma2(u64 a, u64 b, u64 c) {
    u64 d;
    asm("fma.rn.f32x2 %0, %1, %2, %3;" : "=l"(d) : "l"(a), "l"(b), "l"(c));
    return d;
}

__global__ void __launch_bounds__(256)
k_gemm(const float* __restrict__ Wm, const float* __restrict__ bias,
       const float* __restrict__ res, float* __restrict__ out) {
    extern __shared__ float sh[];
    float* As = sh;                 // [128][SW], row-major (k contiguous)
    float* Wt = sh + 128 * SW;      // [128][SW], TRANSPOSED: Wt[j*SW + k] = W[k][j]

    int tid = threadIdx.x;
    int rowBase = blockIdx.x * 128;

    // load + transpose W into smem
    const float4* W4 = (const float4*)Wm;
#pragma unroll
    for (int i = 0; i < 16; i++) {
        int f = tid + i * 256;      // float4 id 0..4095
        int k = f >> 5;             // W row (k index)
        int j0 = (f & 31) * 4;      // W col
        float4 v = __ldg(&W4[f]);
        Wt[(j0 + 0) * SW + k] = v.x;
        Wt[(j0 + 1) * SW + k] = v.y;
        Wt[(j0 + 2) * SW + k] = v.z;
        Wt[(j0 + 3) * SW + k] = v.w;
    }

    // load A tile
    const float4* A4 = (const float4*)g_agg;
#pragma unroll
    for (int i = 0; i < 16; i++) {
        int f = tid + i * 256;
        int row = f >> 5;
        int kq = f & 31;
        int grow = rowBase + row;
        float4 v = make_float4(0.f, 0.f, 0.f, 0.f);
        if (grow < NN) v = __ldg(&A4[(size_t)grow * 32 + kq]);
        *((float4*)&As[row * SW + kq * 4]) = v;
    }
    __syncthreads();

    int tx = tid & 15, ty = tid >> 4;
    int r0 = ty * 8;                // 8 rows per thread
    // 8 columns per thread: c = tx + 16*m  (bank-conflict-friendly for Wt reads)

    u64 acc[8][8];
#pragma unroll
    for (int i = 0; i < 8; i++)
#pragma unroll
        for (int m = 0; m < 8; m++) acc[i][m] = 0ull;

#pragma unroll 2
    for (int k = 0; k < 128; k += 4) {
        ulonglong2 a4[8], w4[8];
#pragma unroll
        for (int i = 0; i < 8; i++)
            a4[i] = *((const ulonglong2*)&As[(r0 + i) * SW + k]);
#pragma unroll
        for (int m = 0; m < 8; m++)
            w4[m] = *((const ulonglong2*)&Wt[(tx + 16 * m) * SW + k]);
#pragma unroll
        for (int i = 0; i < 8; i++)
#pragma unroll
            for (int m = 0; m < 8; m++) {
                acc[i][m] = fma2(a4[i].x, w4[m].x, acc[i][m]);
                acc[i][m] = fma2(a4[i].y, w4[m].y, acc[i][m]);
            }
    }

    // epilogue: reduce packed pair, + residual + bias
    float bv[8];
#pragma unroll
    for (int m = 0; m < 8; m++) bv[m] = __ldg(&bias[tx + 16 * m]);

#pragma unroll
    for (int i = 0; i < 8; i++) {
        int grow = rowBase + r0 + i;
        if (grow < NN) {
            const float* rp = &res[(size_t)grow * DM];
            float* op = &out[(size_t)grow * DM];
#pragma unroll
            for (int m = 0; m < 8; m++) {
                int c = tx + 16 * m;
                float2 p = *((float2*)&acc[i][m]);
                op[c] = __ldg(&rp[c]) + p.x + p.y + bv[m];
            }
        }
    }
}

// ---------------- launch ----------------
extern "C" void kernel_launch(void* const* d_in, const int* in_sizes, int n_in,
                              void* d_out, int out_size) {
    const float* nodes     = (const float*)d_in[0];
    const int*   senders   = (const int*)d_in[1];
    const int*   receivers = (const int*)d_in[2];
    const float* edges     = (const float*)d_in[3];
    const float* W1 = (const float*)d_in[4];
    const float* b1 = (const float*)d_in[5];
    const float* W2 = (const float*)d_in[6];
    const float* b2 = (const float*)d_in[7];
    float* out = (float*)d_out;

    float* buf1 = nullptr;
    cudaGetSymbolAddress((void**)&buf1, g_buf1);

    const size_t SMEM_GEMM = (size_t)(2 * 128 * SW) * sizeof(float);  // 132 KB
    cudaFuncSetAttribute(k_gemm, cudaFuncAttributeMaxDynamicSharedMemorySize,
                         (int)SMEM_GEMM);

    const int T = 256;
    // CSR + degree build (shared by both layers)
    k_zero<<<(NN + T - 1) / T, T>>>();
    k_deg<<<(NE + T - 1) / T, T>>>(senders, receivers, edges);
    k_dis<<<(NN + T - 1) / T, T>>>();
    k_scan1<<<SNB, SCB>>>();
    k_scan2<<<1, 512>>>();
    k_scan3<<<SNB, SCB>>>();
    k_fill<<<(NE + T - 1) / T, T>>>(senders, receivers, edges);

    const int AGG_GRID = (NN * 32 + T - 1) / T;   // one warp per node
    const int GEMM_GRID = (NN + 127) / 128;

    // layer 1: nodes -> buf1
    k_agg<<<AGG_GRID, T>>>(nodes);
    k_gemm<<<GEMM_GRID, T, SMEM_GEMM>>>(W1, b1, nodes, buf1);

    // layer 2: buf1 -> out
    k_agg<<<AGG_GRID, T>>>(buf1);
    k_gemm<<<GEMM_GRID, T, SMEM_GEMM>>>(W2, b2, buf1, out);
}